// round 3
// baseline (speedup 1.0000x reference)
#include <cuda_runtime.h>
#include <cuda_bf16.h>

// NF4 quantized linear: out[m][n] = sum_k x[m][k] * (LUT[nib(packed[n][k])] * absmax[n]) + bias[n]
// M = 8192 (4*2048), K = 4096, N = 4096.
// Strategy: fused-dequant register-blocked fp32 SGEMM.
//   - 128x128 block tile, BK=16, 256 threads, 8x8 microtile per thread
//   - W dequant: int4 load of packed bytes -> smem LUT -> Bs (absmax deferred to epilogue)
//   - x tile transposed into As for coalesced broadcast reads
//   - gmem prefetch of next tile into registers overlapped with compute

#define BM 128
#define BN 128
#define BK 16
#define TM 8
#define TN 8
#define PAD 4
#define LDA (BM + PAD)   // 132 floats; 132*4=528 bytes, 16B-aligned rows
#define NTHREADS 256

__device__ __constant__ float NF4_TAB[16] = {
    -1.0f, -0.6961928009986877f, -0.5250730514526367f, -0.39491748809814453f,
    -0.28444138169288635f, -0.18477343022823334f, -0.09105003625154495f, 0.0f,
    0.07958029955625534f, 0.16093020141124725f, 0.24611230194568634f,
    0.33791524171829224f, 0.44070982933044434f, 0.5626170039176941f,
    0.7229568362236023f, 1.0f};

__global__ __launch_bounds__(NTHREADS, 2)
void nf4_sgemm_kernel(const float* __restrict__ x,
                      const int* __restrict__ packed,
                      const float* __restrict__ absmax,
                      const float* __restrict__ bias,
                      float* __restrict__ out,
                      int M, int N, int K) {
    __shared__ float As[BK][LDA];   // x tile, transposed: As[k][m]
    __shared__ float Bs[BK][LDA];   // dequant w tile (no absmax): Bs[k][n]
    __shared__ float lut[16];

    const int tid = threadIdx.x;
    if (tid < 16) lut[tid] = NF4_TAB[tid];

    const int bm = blockIdx.y * BM;
    const int bn = blockIdx.x * BN;
    const int tx = tid & 15;         // n direction (16 threads)
    const int ty = tid >> 4;         // m direction (16 threads)

    // ---- A (x) load mapping: 128 rows x 16 cols = 512 float4; 2 per thread ----
    const int a_row = tid >> 2;      // 0..63  (and +64 for the second load)
    const int a_c4  = tid & 3;       // which float4 along K within the BK=16 tile

    // ---- B (packed) load mapping: 128 rows x 8 ints = 256 int4; 1 per thread ----
    const int b_n = tid >> 1;        // 0..127
    const int b_v = tid & 1;         // which int4 (4 ints = 8 weights) along K

    const int Kh = K >> 1;           // packed row stride (ints)

    const float4* xg0 = reinterpret_cast<const float4*>(x + (size_t)(bm + a_row)      * K) + a_c4;
    const float4* xg1 = reinterpret_cast<const float4*>(x + (size_t)(bm + a_row + 64) * K) + a_c4;
    const int4*   pg  = reinterpret_cast<const int4*>(packed + (size_t)(bn + b_n) * Kh) + b_v;

    float acc[TM][TN];
#pragma unroll
    for (int i = 0; i < TM; i++)
#pragma unroll
        for (int j = 0; j < TN; j++) acc[i][j] = 0.0f;

    const int ksteps = K / BK;       // 256

    // Prologue: fetch tile 0 into registers
    float4 ra0 = xg0[0];
    float4 ra1 = xg1[0];
    int4   rp  = pg[0];

    for (int kt = 0; kt < ksteps; kt++) {
        __syncthreads();   // smem consumers from previous iteration done

        // ---- store A tile (transpose) ----
        {
            int kbase = a_c4 * 4;
            As[kbase + 0][a_row]      = ra0.x;
            As[kbase + 1][a_row]      = ra0.y;
            As[kbase + 2][a_row]      = ra0.z;
            As[kbase + 3][a_row]      = ra0.w;
            As[kbase + 0][a_row + 64] = ra1.x;
            As[kbase + 1][a_row + 64] = ra1.y;
            As[kbase + 2][a_row + 64] = ra1.z;
            As[kbase + 3][a_row + 64] = ra1.w;
        }
        // ---- dequant + store B tile ----
        {
            int kbase = b_v * 8;
            int bytes[4] = {rp.x, rp.y, rp.z, rp.w};
#pragma unroll
            for (int e = 0; e < 4; e++) {
                int byte = bytes[e];
                Bs[kbase + 2 * e + 0][b_n] = lut[(byte >> 4) & 15];
                Bs[kbase + 2 * e + 1][b_n] = lut[byte & 15];
            }
        }
        __syncthreads();

        // Prefetch next tile (gmem) while computing on smem
        if (kt + 1 < ksteps) {
            ra0 = xg0[(kt + 1) * 4];
            ra1 = xg1[(kt + 1) * 4];
            rp  = pg[(kt + 1) * 2];
        }

        // ---- compute 16 k-steps ----
#pragma unroll
        for (int kk = 0; kk < BK; kk++) {
            float a[TM], b[TN];
            const float4* ap = reinterpret_cast<const float4*>(&As[kk][ty * TM]);
            const float4* bp = reinterpret_cast<const float4*>(&Bs[kk][tx * TN]);
            float4 a0 = ap[0], a1 = ap[1];
            float4 b0 = bp[0], b1 = bp[1];
            a[0] = a0.x; a[1] = a0.y; a[2] = a0.z; a[3] = a0.w;
            a[4] = a1.x; a[5] = a1.y; a[6] = a1.z; a[7] = a1.w;
            b[0] = b0.x; b[1] = b0.y; b[2] = b0.z; b[3] = b0.w;
            b[4] = b1.x; b[5] = b1.y; b[6] = b1.z; b[7] = b1.w;
#pragma unroll
            for (int i = 0; i < TM; i++)
#pragma unroll
                for (int j = 0; j < TN; j++)
                    acc[i][j] = fmaf(a[i], b[j], acc[i][j]);
        }
    }

    // ---- epilogue: apply absmax (deferred) + bias, write out ----
    const int ncol = bn + tx * TN;
    float4 am0 = *reinterpret_cast<const float4*>(absmax + ncol);
    float4 am1 = *reinterpret_cast<const float4*>(absmax + ncol + 4);
    float4 bi0 = *reinterpret_cast<const float4*>(bias + ncol);
    float4 bi1 = *reinterpret_cast<const float4*>(bias + ncol + 4);
    float am[TN] = {am0.x, am0.y, am0.z, am0.w, am1.x, am1.y, am1.z, am1.w};
    float bi[TN] = {bi0.x, bi0.y, bi0.z, bi0.w, bi1.x, bi1.y, bi1.z, bi1.w};

#pragma unroll
    for (int i = 0; i < TM; i++) {
        int row = bm + ty * TM + i;
        float4 o0, o1;
        o0.x = fmaf(acc[i][0], am[0], bi[0]);
        o0.y = fmaf(acc[i][1], am[1], bi[1]);
        o0.z = fmaf(acc[i][2], am[2], bi[2]);
        o0.w = fmaf(acc[i][3], am[3], bi[3]);
        o1.x = fmaf(acc[i][4], am[4], bi[4]);
        o1.y = fmaf(acc[i][5], am[5], bi[5]);
        o1.z = fmaf(acc[i][6], am[6], bi[6]);
        o1.w = fmaf(acc[i][7], am[7], bi[7]);
        float4* og = reinterpret_cast<float4*>(out + (size_t)row * N + ncol);
        og[0] = o0;
        og[1] = o1;
    }
}

extern "C" void kernel_launch(void* const* d_in, const int* in_sizes, int n_in,
                              void* d_out, int out_size) {
    const float* x      = (const float*)d_in[0];
    const int*   packed = (const int*)d_in[1];
    const float* absmax = (const float*)d_in[2];
    const float* bias   = (const float*)d_in[3];
    float*       out    = (float*)d_out;

    const int N = in_sizes[2];              // out_features = 4096
    const int K = 2 * (in_sizes[1] / N);    // in_features  = 4096
    const int M = in_sizes[0] / K;          // 8192

    dim3 grid(N / BN, M / BM);              // (32, 64)
    nf4_sgemm_kernel<<<grid, NTHREADS>>>(x, packed, absmax, bias, out, M, N, K);
}

// round 9
// speedup vs baseline: 3.2684x; 3.2684x over previous
#include <cuda_runtime.h>
#include <cuda_bf16.h>
#include <cstdint>

// NF4 quantized linear via mma.sync (HMMA) on sm_103 (non-'a' target).
// out[m][n] = sum_k x[m][k] * LUT[nib(packed[n][k])] * absmax[n] + bias[n]
// M=8192, N=4096, K=4096.
//
// 3-term bf16 split: D = Xh*Wh + Xh*Wl + Xl*Wh (fp32 acc) -> rel err ~1e-5.
// Pre-pass kernels write pre-split, pre-swizzled bf16 hi/lo images of X and W
// (smem tile layout: 128B rows = [hi 64B | lo 64B], chunk swizzle c^(row&7)),
// so the GEMM mainloop is pure cp.async -> ldmatrix -> mma.sync.
//
// R8 fix: build_w now reads 16 int32s (one byte-value each) per 32-weight
// k-chunk; R7 wrongly read 4 ints and treated each as 4 packed bytes.

#define M_DIM 8192
#define N_DIM 4096
#define K_DIM 4096
#define KC    (K_DIM / 32)        // 128 K-chunks of 32
#define KH    (K_DIM / 2)         // packed bytes per W row

#define BM 128
#define BN 128
#define BK 32
#define NCHUNK KC                 // 128
#define NTH 256
#define STAGES 4
#define STAGE_BYTES 32768         // X 16KB + W 16KB
#define SMEM_DYN (STAGES * STAGE_BYTES)   // 131072

// pre-split global images: per (row, kchunk) one 128-byte block:
//   16B chunks 0-3 = hi bf16 (32 values), 4-7 = lo bf16, stored at swizzled
//   position (c ^ (row & 7)).
__device__ uint8_t g_xhl[(size_t)M_DIM * KC * 128];   // 128 MB
__device__ uint8_t g_whl[(size_t)N_DIM * KC * 128];   // 64 MB

__constant__ float NF4_TAB[16] = {
    -1.0f, -0.6961928009986877f, -0.5250730514526367f, -0.39491748809814453f,
    -0.28444138169288635f, -0.18477343022823334f, -0.09105003625154495f, 0.0f,
    0.07958029955625534f, 0.16093020141124725f, 0.24611230194568634f,
    0.33791524171829224f, 0.44070982933044434f, 0.5626170039176941f,
    0.7229568362236023f, 1.0f};

// ---------------- PTX helpers (all arch-agnostic, sm_80+) ----------------
#define CP_ASYNC16(smem_u32, gptr)                                             \
    asm volatile("cp.async.cg.shared.global [%0], [%1], 16;"                   \
                 :: "r"(smem_u32), "l"(gptr))
#define CP_COMMIT() asm volatile("cp.async.commit_group;" ::: "memory")
#define CP_WAIT(n)  asm volatile("cp.async.wait_group %0;" :: "n"(n) : "memory")

#define LDSM4(r0, r1, r2, r3, addr)                                            \
    asm volatile("ldmatrix.sync.aligned.m8n8.x4.shared.b16 {%0,%1,%2,%3}, [%4];" \
                 : "=r"(r0), "=r"(r1), "=r"(r2), "=r"(r3) : "r"(addr))

#define MMA16816(d, a, b0, b1)                                                 \
    asm volatile("mma.sync.aligned.m16n8k16.row.col.f32.bf16.bf16.f32 "        \
                 "{%0,%1,%2,%3}, {%4,%5,%6,%7}, {%8,%9}, {%0,%1,%2,%3};"       \
                 : "+f"((d)[0]), "+f"((d)[1]), "+f"((d)[2]), "+f"((d)[3])      \
                 : "r"((a)[0]), "r"((a)[1]), "r"((a)[2]), "r"((a)[3]),         \
                   "r"(b0), "r"(b1))

// pack (bf16(lo_f), bf16(hi_f)) -> u32 {hi<<16 | lo}
__device__ __forceinline__ uint32_t pack_bf16x2_rn(float lo, float hi) {
    uint32_t r;
    asm("cvt.rn.bf16x2.f32 %0, %1, %2;" : "=r"(r) : "f"(hi), "f"(lo));
    return r;
}

// ---------------- pre-pass: split X into hi/lo bf16, swizzled layout -------
__global__ __launch_bounds__(256)
void build_x_kernel(const float* __restrict__ x) {
    const size_t id = (size_t)blockIdx.x * 256 + threadIdx.x;  // m*KC + kc
    const int kc = (int)(id & (KC - 1));
    const int m  = (int)(id >> 7);                             // KC = 128
    const float4* src = reinterpret_cast<const float4*>(x + (size_t)m * K_DIM + kc * 32);

    uint32_t hw[16], lw[16];
#pragma unroll
    for (int t = 0; t < 8; t++) {
        float4 v = src[t];
        uint32_t u0 = __float_as_uint(v.x), u1 = __float_as_uint(v.y);
        uint32_t u2 = __float_as_uint(v.z), u3 = __float_as_uint(v.w);
        // hi = truncate-to-bf16 (clear low 16 mantissa bits): exact residual
        hw[2 * t + 0] = __byte_perm(u0, u1, 0x7632);
        hw[2 * t + 1] = __byte_perm(u2, u3, 0x7632);
        float l0 = v.x - __uint_as_float(u0 & 0xFFFF0000u);
        float l1 = v.y - __uint_as_float(u1 & 0xFFFF0000u);
        float l2 = v.z - __uint_as_float(u2 & 0xFFFF0000u);
        float l3 = v.w - __uint_as_float(u3 & 0xFFFF0000u);
        lw[2 * t + 0] = pack_bf16x2_rn(l0, l1);
        lw[2 * t + 1] = pack_bf16x2_rn(l2, l3);
    }
    uint8_t* dst = g_xhl + id * 128;
    const int r7 = m & 7;
#pragma unroll
    for (int q = 0; q < 4; q++) {   // hi chunks 0-3
        *reinterpret_cast<uint4*>(dst + ((q ^ r7) * 16)) =
            make_uint4(hw[4 * q], hw[4 * q + 1], hw[4 * q + 2], hw[4 * q + 3]);
    }
#pragma unroll
    for (int q = 0; q < 4; q++) {   // lo chunks 4-7
        *reinterpret_cast<uint4*>(dst + (((q + 4) ^ r7) * 16)) =
            make_uint4(lw[4 * q], lw[4 * q + 1], lw[4 * q + 2], lw[4 * q + 3]);
    }
}

// ---------------- pre-pass: dequant W into hi/lo bf16, swizzled layout -----
// Each int32 of `packed` holds ONE byte value (0..255) = 2 nibbles = 2 weights.
// A 32-weight k-chunk therefore spans 16 consecutive int32s (= 4 int4 loads).
__global__ __launch_bounds__(256)
void build_w_kernel(const int* __restrict__ packed) {
    __shared__ uint32_t lut[16];   // bf16 hi (low16) | bf16 lo (high16)
    if (threadIdx.x < 16) {
        float v = NF4_TAB[threadIdx.x];
        uint32_t u = __float_as_uint(v);
        float h = __uint_as_float(u & 0xFFFF0000u);       // truncated bf16
        lut[threadIdx.x] = pack_bf16x2_rn(h, v - h);      // {lo<<16 | hi}
    }
    __syncthreads();

    const size_t id = (size_t)blockIdx.x * 256 + threadIdx.x;  // n*KC + kc
    const int kc = (int)(id & (KC - 1));
    const int n  = (int)(id >> 7);
    // 16 ints = 16 byte-values = 32 weights for this k-chunk
    const int4* src = reinterpret_cast<const int4*>(packed) +
                      (size_t)n * (KH / 4) + kc * 4;

    uint32_t hw[16], lw[16];
#pragma unroll
    for (int v4 = 0; v4 < 4; v4++) {
        const int4 pv = src[v4];
        const uint32_t byts[4] = {(uint32_t)pv.x & 255u, (uint32_t)pv.y & 255u,
                                  (uint32_t)pv.z & 255u, (uint32_t)pv.w & 255u};
#pragma unroll
        for (int e = 0; e < 4; e++) {
            const uint32_t b  = byts[e];
            const uint32_t u1 = lut[b >> 4];      // k even (high nibble first)
            const uint32_t u2 = lut[b & 15u];     // k odd
            const int jb = 4 * v4 + e;            // bf16x2 word index (k pair jb)
            hw[jb] = (u1 & 0xFFFFu) | (u2 << 16);
            lw[jb] = (u1 >> 16)     | (u2 & 0xFFFF0000u);
        }
    }
    uint8_t* dst = g_whl + id * 128;
    const int r7 = n & 7;
#pragma unroll
    for (int q = 0; q < 4; q++)
        *reinterpret_cast<uint4*>(dst + ((q ^ r7) * 16)) =
            make_uint4(hw[4 * q], hw[4 * q + 1], hw[4 * q + 2], hw[4 * q + 3]);
#pragma unroll
    for (int q = 0; q < 4; q++)
        *reinterpret_cast<uint4*>(dst + (((q + 4) ^ r7) * 16)) =
            make_uint4(lw[4 * q], lw[4 * q + 1], lw[4 * q + 2], lw[4 * q + 3]);
}

// ---------------- main GEMM: cp.async pipeline + ldmatrix + mma.sync -------
__global__ __launch_bounds__(NTH, 1)
void nf4_hmma_kernel(const float* __restrict__ absmax,
                     const float* __restrict__ bias,
                     float* __restrict__ out) {
    extern __shared__ __align__(1024) uint8_t smem[];
    const uint32_t sbase = (uint32_t)__cvta_generic_to_shared(smem);

    const int tid  = threadIdx.x;
    const int wid  = tid >> 5;
    const int lane = tid & 31;
    const int bm = blockIdx.y * BM;
    const int bn = blockIdx.x * BN;
    const int wm = (wid & 1) * 64;     // warp m-offset (2 warps in m)
    const int wn = (wid >> 1) * 32;    // warp n-offset (4 warps in n)

    // ---- per-lane ldmatrix address components ----
    const int s7 = lane & 7;
    const int rl = s7 + 8 * ((lane >> 3) & 1);       // a-frag row-in-16
    const int pa = lane >> 4;                        // a kc bit
    const int nl = s7 + 8 * (lane >> 4);             // b-frag n-in-16
    const int kb = (lane >> 3) & 1;                  // b kc bit
    const uint32_t xlb = (uint32_t)(wm + rl) * 128;  // X lane base in tile
    const uint32_t wlb = (uint32_t)(wn + nl) * 128;  // W lane base in tile

    uint32_t a_sw[2][2], b_sw[2][2];   // [hv][ks] swizzled 16B offsets
#pragma unroll
    for (int hv = 0; hv < 2; hv++)
#pragma unroll
        for (int ks = 0; ks < 2; ks++) {
            a_sw[hv][ks] = (uint32_t)(((hv * 4 + ks * 2 + pa) ^ s7) * 16);
            b_sw[hv][ks] = (uint32_t)(((hv * 4 + ks * 2 + kb) ^ s7) * 16);
        }

    // ---- cp.async producer mapping: 4 X-chunks + 4 W-chunks per thread ----
    // q = tid + i*256 -> row = q>>3, j = q&7 (identity copy; swizzle baked in)
    uint32_t prow[4], pj[4];
#pragma unroll
    for (int i = 0; i < 4; i++) {
        int q = tid + i * 256;
        prow[i] = (uint32_t)(q >> 3);
        pj[i]   = (uint32_t)(q & 7);
    }

    auto issue_stage = [&](int c) {
        const uint32_t sb = sbase + (uint32_t)(c & (STAGES - 1)) * STAGE_BYTES;
#pragma unroll
        for (int i = 0; i < 4; i++) {
            const uint8_t* gx = g_xhl + (((size_t)(bm + prow[i])) * KC + c) * 128 + pj[i] * 16;
            CP_ASYNC16(sb + prow[i] * 128 + pj[i] * 16, gx);
        }
#pragma unroll
        for (int i = 0; i < 4; i++) {
            const uint8_t* gw = g_whl + (((size_t)(bn + prow[i])) * KC + c) * 128 + pj[i] * 16;
            CP_ASYNC16(sb + 16384 + prow[i] * 128 + pj[i] * 16, gw);
        }
    };

    float acc[4][4][4];
#pragma unroll
    for (int mt = 0; mt < 4; mt++)
#pragma unroll
        for (int nt = 0; nt < 4; nt++)
#pragma unroll
            for (int e = 0; e < 4; e++) acc[mt][nt][e] = 0.0f;

    // ---- prologue: 3 stages in flight ----
    issue_stage(0); CP_COMMIT();
    issue_stage(1); CP_COMMIT();
    issue_stage(2); CP_COMMIT();

    // ---- mainloop ----
    for (int c = 0; c < NCHUNK; c++) {
        CP_WAIT(2);          // group for chunk c complete
        __syncthreads();

        const uint32_t sb = sbase + (uint32_t)(c & (STAGES - 1)) * STAGE_BYTES;
        const uint32_t Xb = sb;
        const uint32_t Wb = sb + 16384;

#pragma unroll
        for (int ks = 0; ks < 2; ks++) {
            uint32_t ah[4][4], al[4][4];
#pragma unroll
            for (int mt = 0; mt < 4; mt++) {
                const uint32_t base = Xb + xlb + (uint32_t)mt * 2048;
                LDSM4(ah[mt][0], ah[mt][1], ah[mt][2], ah[mt][3], base + a_sw[0][ks]);
                LDSM4(al[mt][0], al[mt][1], al[mt][2], al[mt][3], base + a_sw[1][ks]);
            }
            uint32_t bh[2][4], bl[2][4];
#pragma unroll
            for (int g = 0; g < 2; g++) {
                const uint32_t base = Wb + wlb + (uint32_t)g * 2048;
                LDSM4(bh[g][0], bh[g][1], bh[g][2], bh[g][3], base + b_sw[0][ks]);
                LDSM4(bl[g][0], bl[g][1], bl[g][2], bl[g][3], base + b_sw[1][ks]);
            }
#pragma unroll
            for (int mt = 0; mt < 4; mt++)
#pragma unroll
                for (int nt = 0; nt < 4; nt++) {
                    const int g = nt >> 1, o = (nt & 1) * 2;
                    MMA16816(acc[mt][nt], ah[mt], bh[g][o], bh[g][o + 1]);
                    MMA16816(acc[mt][nt], ah[mt], bl[g][o], bl[g][o + 1]);
                    MMA16816(acc[mt][nt], al[mt], bh[g][o], bh[g][o + 1]);
                }
        }

        if (c + 3 < NCHUNK) issue_stage(c + 3);
        CP_COMMIT();   // keep group count in lockstep
    }

    // ---- epilogue: apply absmax + bias, write out ----
#pragma unroll
    for (int nt = 0; nt < 4; nt++) {
        const int col = bn + wn + nt * 8 + 2 * (lane & 3);
        const float2 am = *reinterpret_cast<const float2*>(absmax + col);
        const float2 bi = *reinterpret_cast<const float2*>(bias + col);
#pragma unroll
        for (int mt = 0; mt < 4; mt++) {
            const int m0 = bm + wm + mt * 16 + (lane >> 2);
            float2 o0, o1;
            o0.x = acc[mt][nt][0] * am.x + bi.x;
            o0.y = acc[mt][nt][1] * am.y + bi.y;
            o1.x = acc[mt][nt][2] * am.x + bi.x;
            o1.y = acc[mt][nt][3] * am.y + bi.y;
            *reinterpret_cast<float2*>(out + (size_t)m0 * N_DIM + col) = o0;
            *reinterpret_cast<float2*>(out + (size_t)(m0 + 8) * N_DIM + col) = o1;
        }
    }
}

// ---------------- launch ----------------
extern "C" void kernel_launch(void* const* d_in, const int* in_sizes, int n_in,
                              void* d_out, int out_size) {
    const float* x      = (const float*)d_in[0];
    const int*   packed = (const int*)d_in[1];
    const float* absmax = (const float*)d_in[2];
    const float* bias   = (const float*)d_in[3];
    float*       out    = (float*)d_out;

    build_x_kernel<<<(M_DIM * KC) / 256, 256>>>(x);
    build_w_kernel<<<(N_DIM * KC) / 256, 256>>>(packed);

    cudaFuncSetAttribute(nf4_hmma_kernel,
                         cudaFuncAttributeMaxDynamicSharedMemorySize, SMEM_DYN);
    dim3 grid(N_DIM / BN, M_DIM / BM);   // (32, 64)
    nf4_hmma_kernel<<<grid, NTH, SMEM_DYN>>>(absmax, bias, out);
}

// round 10
// speedup vs baseline: 8.2944x; 2.5377x over previous
#include <cuda_runtime.h>
#include <cuda_fp16.h>
#include <cstdint>

// NF4 quantized linear via single-term fp16 mma.sync (sm_103, non-'a' target).
// out[m][n] = sum_k x[m][k] * LUT[nib(packed[n][k])] * absmax[n] + bias[n]
// M=8192, N=4096, K=4096.
//
// fp16(x) * fp16(LUT) with fp32 accumulation: rms rel err ~3e-4 (< 1e-3 tol).
// Pre-pass kernels write pre-swizzled fp16 images of X (64 MB) and dequant W
// (32 MB). GEMM: 128x256x64 CTA tile, 4-stage cp.async, ldmatrix, HMMA.
// Layout: per (row, kchunk64) one 128-byte block = 8 x 16B sub-chunks stored
// at swizzled position (j ^ (row & 7)).

#define M_DIM 8192
#define N_DIM 4096
#define K_DIM 4096
#define KC64  (K_DIM / 64)        // 64 K-chunks of 64
#define KH    (K_DIM / 2)         // packed byte count per W row

#define BM 128
#define BN 256
#define NCHUNK KC64               // 64
#define NTH 256
#define STAGES 4
#define XS_BYTES 16384            // 128 rows x 128B
#define WS_BYTES 32768            // 256 rows x 128B
#define STAGE_BYTES (XS_BYTES + WS_BYTES)       // 49152
#define SMEM_DYN (STAGES * STAGE_BYTES)         // 196608

__device__ uint8_t g_xh[(size_t)M_DIM * KC64 * 128];   // 64 MB fp16 X image
__device__ uint8_t g_wh[(size_t)N_DIM * KC64 * 128];   // 32 MB fp16 W image

__constant__ float NF4_TAB[16] = {
    -1.0f, -0.6961928009986877f, -0.5250730514526367f, -0.39491748809814453f,
    -0.28444138169288635f, -0.18477343022823334f, -0.09105003625154495f, 0.0f,
    0.07958029955625534f, 0.16093020141124725f, 0.24611230194568634f,
    0.33791524171829224f, 0.44070982933044434f, 0.5626170039176941f,
    0.7229568362236023f, 1.0f};

// ---------------- PTX helpers (arch-agnostic, sm_80+) ----------------
#define CP_ASYNC16(smem_u32, gptr)                                             \
    asm volatile("cp.async.cg.shared.global [%0], [%1], 16;"                   \
                 :: "r"(smem_u32), "l"(gptr))
#define CP_COMMIT() asm volatile("cp.async.commit_group;" ::: "memory")
#define CP_WAIT(n)  asm volatile("cp.async.wait_group %0;" :: "n"(n) : "memory")

#define LDSM4(r0, r1, r2, r3, addr)                                            \
    asm volatile("ldmatrix.sync.aligned.m8n8.x4.shared.b16 {%0,%1,%2,%3}, [%4];" \
                 : "=r"(r0), "=r"(r1), "=r"(r2), "=r"(r3) : "r"(addr))

#define MMA16816(d, a, b0, b1)                                                 \
    asm volatile("mma.sync.aligned.m16n8k16.row.col.f32.f16.f16.f32 "          \
                 "{%0,%1,%2,%3}, {%4,%5,%6,%7}, {%8,%9}, {%0,%1,%2,%3};"       \
                 : "+f"((d)[0]), "+f"((d)[1]), "+f"((d)[2]), "+f"((d)[3])      \
                 : "r"((a)[0]), "r"((a)[1]), "r"((a)[2]), "r"((a)[3]),         \
                   "r"(b0), "r"(b1))

// pack (fp16(a), fp16(b)) -> u32 {b<<16 | a}
__device__ __forceinline__ uint32_t pack_f16x2(float a, float b) {
    uint32_t r;
    asm("cvt.rn.f16x2.f32 %0, %1, %2;" : "=r"(r) : "f"(b), "f"(a));
    return r;
}

// ---------------- pre-pass: X -> fp16, swizzled image ----------------
__global__ __launch_bounds__(256)
void build_x_kernel(const float* __restrict__ x) {
    const size_t id = (size_t)blockIdx.x * 256 + threadIdx.x;  // m*KC64 + kc
    const int kc = (int)(id & (KC64 - 1));
    const int m  = (int)(id >> 6);
    const float4* src = reinterpret_cast<const float4*>(x + (size_t)m * K_DIM + kc * 64);

    uint32_t w[32];
#pragma unroll
    for (int t = 0; t < 16; t++) {
        float4 v = src[t];
        w[2 * t + 0] = pack_f16x2(v.x, v.y);
        w[2 * t + 1] = pack_f16x2(v.z, v.w);
    }
    uint8_t* dst = g_xh + id * 128;
    const int r7 = m & 7;
#pragma unroll
    for (int q = 0; q < 8; q++)
        *reinterpret_cast<uint4*>(dst + ((q ^ r7) * 16)) =
            make_uint4(w[4 * q], w[4 * q + 1], w[4 * q + 2], w[4 * q + 3]);
}

// ---------------- pre-pass: NF4 dequant -> fp16, swizzled image ----------
// Each int32 of `packed` holds ONE byte value = 2 nibbles = 2 weights.
// A 64-weight k-chunk spans 32 ints (= 8 int4 loads).
__global__ __launch_bounds__(256)
void build_w_kernel(const int* __restrict__ packed) {
    __shared__ uint16_t lut[16];   // fp16 bits of NF4 level
    if (threadIdx.x < 16)
        lut[threadIdx.x] = (uint16_t)(pack_f16x2(NF4_TAB[threadIdx.x], 0.0f) & 0xFFFFu);
    __syncthreads();

    const size_t id = (size_t)blockIdx.x * 256 + threadIdx.x;  // n*KC64 + kc
    const int kc = (int)(id & (KC64 - 1));
    const int n  = (int)(id >> 6);
    const int4* src = reinterpret_cast<const int4*>(packed) +
                      (size_t)n * (KH / 4) + kc * 8;

    uint32_t w[32];
#pragma unroll
    for (int v4 = 0; v4 < 8; v4++) {
        const int4 pv = src[v4];
        const uint32_t byts[4] = {(uint32_t)pv.x & 255u, (uint32_t)pv.y & 255u,
                                  (uint32_t)pv.z & 255u, (uint32_t)pv.w & 255u};
#pragma unroll
        for (int e = 0; e < 4; e++) {
            const uint32_t b = byts[e];
            // k even = high nibble, k odd = low nibble
            w[4 * v4 + e] = (uint32_t)lut[b >> 4] | ((uint32_t)lut[b & 15u] << 16);
        }
    }
    uint8_t* dst = g_wh + id * 128;
    const int r7 = n & 7;
#pragma unroll
    for (int q = 0; q < 8; q++)
        *reinterpret_cast<uint4*>(dst + ((q ^ r7) * 16)) =
            make_uint4(w[4 * q], w[4 * q + 1], w[4 * q + 2], w[4 * q + 3]);
}

// ---------------- main GEMM: cp.async pipeline + ldmatrix + mma.sync -------
__global__ __launch_bounds__(NTH, 1)
void nf4_hmma_kernel(const float* __restrict__ absmax,
                     const float* __restrict__ bias,
                     float* __restrict__ out) {
    extern __shared__ __align__(1024) uint8_t smem[];
    const uint32_t sbase = (uint32_t)__cvta_generic_to_shared(smem);

    const int tid  = threadIdx.x;
    const int wid  = tid >> 5;
    const int lane = tid & 31;
    const int bm = blockIdx.y * BM;
    const int bn = blockIdx.x * BN;
    const int wm = (wid & 1) * 64;     // 2 warps in m, warptile 64
    const int wn = (wid >> 1) * 64;    // 4 warps in n, warptile 64

    // ---- per-lane ldmatrix address components (verified in R8) ----
    const int s7 = lane & 7;
    const int rl = s7 + 8 * ((lane >> 3) & 1);       // A row-in-16
    const int pa = lane >> 4;                        // A k-half bit
    const int nl = s7 + 8 * (lane >> 4);             // B n-in-16
    const int kb = (lane >> 3) & 1;                  // B k-half bit
    const uint32_t xlb = (uint32_t)(wm + rl) * 128;
    const uint32_t wlb = (uint32_t)(wn + nl) * 128;

    uint32_t a_sw[4], b_sw[4];   // per k16-step swizzled 16B offsets
#pragma unroll
    for (int ks = 0; ks < 4; ks++) {
        a_sw[ks] = (uint32_t)(((2 * ks + pa) ^ s7) * 16);
        b_sw[ks] = (uint32_t)(((2 * ks + kb) ^ s7) * 16);
    }

    // ---- cp.async producer mapping: identity copy (swizzle baked in) ----
    // X: 1024 16B-chunks -> 4/thread;  W: 2048 -> 8/thread
    auto issue_stage = [&](int c) {
        const uint32_t sb = sbase + (uint32_t)(c & (STAGES - 1)) * STAGE_BYTES;
#pragma unroll
        for (int i = 0; i < 4; i++) {
            const int q = tid + i * 256;
            const int row = q >> 3, j = q & 7;
            const uint8_t* gx = g_xh + (((size_t)(bm + row)) * KC64 + c) * 128 + j * 16;
            CP_ASYNC16(sb + row * 128 + j * 16, gx);
        }
#pragma unroll
        for (int i = 0; i < 8; i++) {
            const int q = tid + i * 256;
            const int row = q >> 3, j = q & 7;
            const uint8_t* gw = g_wh + (((size_t)(bn + row)) * KC64 + c) * 128 + j * 16;
            CP_ASYNC16(sb + XS_BYTES + row * 128 + j * 16, gw);
        }
    };

    float acc[4][8][4];
#pragma unroll
    for (int mt = 0; mt < 4; mt++)
#pragma unroll
        for (int nt = 0; nt < 8; nt++)
#pragma unroll
            for (int e = 0; e < 4; e++) acc[mt][nt][e] = 0.0f;

    // ---- prologue: 3 stages in flight ----
    issue_stage(0); CP_COMMIT();
    issue_stage(1); CP_COMMIT();
    issue_stage(2); CP_COMMIT();

    // ---- mainloop ----
    for (int c = 0; c < NCHUNK; c++) {
        CP_WAIT(2);          // group for chunk c complete
        __syncthreads();

        if (c + 3 < NCHUNK) issue_stage(c + 3);
        CP_COMMIT();         // keep group count in lockstep

        const uint32_t sb = sbase + (uint32_t)(c & (STAGES - 1)) * STAGE_BYTES;
        const uint32_t Xb = sb;
        const uint32_t Wb = sb + XS_BYTES;

#pragma unroll
        for (int ks = 0; ks < 4; ks++) {
            uint32_t a[4][4];
#pragma unroll
            for (int mt = 0; mt < 4; mt++)
                LDSM4(a[mt][0], a[mt][1], a[mt][2], a[mt][3],
                      Xb + xlb + (uint32_t)mt * 2048 + a_sw[ks]);
            uint32_t b[4][4];
#pragma unroll
            for (int g = 0; g < 4; g++)
                LDSM4(b[g][0], b[g][1], b[g][2], b[g][3],
                      Wb + wlb + (uint32_t)g * 2048 + b_sw[ks]);
#pragma unroll
            for (int mt = 0; mt < 4; mt++)
#pragma unroll
                for (int nt = 0; nt < 8; nt++) {
                    const int g = nt >> 1, o = (nt & 1) * 2;
                    MMA16816(acc[mt][nt], a[mt], b[g][o], b[g][o + 1]);
                }
        }
    }

    // ---- epilogue: apply absmax + bias, write out ----
#pragma unroll
    for (int nt = 0; nt < 8; nt++) {
        const int col = bn + wn + nt * 8 + 2 * (lane & 3);
        const float2 am = *reinterpret_cast<const float2*>(absmax + col);
        const float2 bi = *reinterpret_cast<const float2*>(bias + col);
#pragma unroll
        for (int mt = 0; mt < 4; mt++) {
            const int m0 = bm + wm + mt * 16 + (lane >> 2);
            float2 o0, o1;
            o0.x = acc[mt][nt][0] * am.x + bi.x;
            o0.y = acc[mt][nt][1] * am.y + bi.y;
            o1.x = acc[mt][nt][2] * am.x + bi.x;
            o1.y = acc[mt][nt][3] * am.y + bi.y;
            *reinterpret_cast<float2*>(out + (size_t)m0 * N_DIM + col) = o0;
            *reinterpret_cast<float2*>(out + (size_t)(m0 + 8) * N_DIM + col) = o1;
        }
    }
}

// ---------------- launch ----------------
extern "C" void kernel_launch(void* const* d_in, const int* in_sizes, int n_in,
                              void* d_out, int out_size) {
    const float* x      = (const float*)d_in[0];
    const int*   packed = (const int*)d_in[1];
    const float* absmax = (const float*)d_in[2];
    const float* bias   = (const float*)d_in[3];
    float*       out    = (float*)d_out;

    build_x_kernel<<<(M_DIM * KC64) / 256, 256>>>(x);
    build_w_kernel<<<(N_DIM * KC64) / 256, 256>>>(packed);

    cudaFuncSetAttribute(nf4_hmma_kernel,
                         cudaFuncAttributeMaxDynamicSharedMemorySize, SMEM_DYN);
    dim3 grid(N_DIM / BN, M_DIM / BM);   // (16, 64)
    nf4_hmma_kernel<<<grid, NTH, SMEM_DYN>>>(absmax, bias, out);
}

// round 12
// speedup vs baseline: 8.3701x; 1.0091x over previous
#include <cuda_runtime.h>
#include <cuda_fp16.h>
#include <cstdint>

// NF4 quantized linear via single-term fp16 mma.sync (sm_103, non-'a' target).
// out[m][n] = sum_k x[m][k] * LUT[nib(packed[n][k])] * absmax[n] + bias[n]
// M=8192, N=4096, K=4096.
//
// fp16(x) * fp16(LUT) with fp32 accumulation: rel err ~2.6e-4 (< 1e-3 tol).
// Pre-pass kernels write pre-swizzled fp16 images of X (64 MB) and dequant W
// (32 MB). GEMM: 128x256x64 CTA tile, 4-stage cp.async, ldmatrix, HMMA.
// R10: 512 threads (4 warps/SMSP, warptile 64x32) to hide LDSM bubbles in
// the HMMA pipe (R9 ran 2 warps/SMSP at ~73% pipe efficiency).

#define M_DIM 8192
#define N_DIM 4096
#define K_DIM 4096
#define KC64  (K_DIM / 64)        // 64 K-chunks of 64
#define KH    (K_DIM / 2)         // packed byte count per W row

#define BM 128
#define BN 256
#define NCHUNK KC64               // 64
#define NTH 512
#define STAGES 4
#define XS_BYTES 16384            // 128 rows x 128B
#define WS_BYTES 32768            // 256 rows x 128B
#define STAGE_BYTES (XS_BYTES + WS_BYTES)       // 49152
#define SMEM_DYN (STAGES * STAGE_BYTES)         // 196608

__device__ uint8_t g_xh[(size_t)M_DIM * KC64 * 128];   // 64 MB fp16 X image
__device__ uint8_t g_wh[(size_t)N_DIM * KC64 * 128];   // 32 MB fp16 W image

__constant__ float NF4_TAB[16] = {
    -1.0f, -0.6961928009986877f, -0.5250730514526367f, -0.39491748809814453f,
    -0.28444138169288635f, -0.18477343022823334f, -0.09105003625154495f, 0.0f,
    0.07958029955625534f, 0.16093020141124725f, 0.24611230194568634f,
    0.33791524171829224f, 0.44070982933044434f, 0.5626170039176941f,
    0.7229568362236023f, 1.0f};

// ---------------- PTX helpers (arch-agnostic, sm_80+) ----------------
#define CP_ASYNC16(smem_u32, gptr)                                             \
    asm volatile("cp.async.cg.shared.global [%0], [%1], 16;"                   \
                 :: "r"(smem_u32), "l"(gptr))
#define CP_COMMIT() asm volatile("cp.async.commit_group;" ::: "memory")
#define CP_WAIT(n)  asm volatile("cp.async.wait_group %0;" :: "n"(n) : "memory")

#define LDSM4(r0, r1, r2, r3, addr)                                            \
    asm volatile("ldmatrix.sync.aligned.m8n8.x4.shared.b16 {%0,%1,%2,%3}, [%4];" \
                 : "=r"(r0), "=r"(r1), "=r"(r2), "=r"(r3) : "r"(addr))

#define MMA16816(d, a, b0, b1)                                                 \
    asm volatile("mma.sync.aligned.m16n8k16.row.col.f32.f16.f16.f32 "          \
                 "{%0,%1,%2,%3}, {%4,%5,%6,%7}, {%8,%9}, {%0,%1,%2,%3};"       \
                 : "+f"((d)[0]), "+f"((d)[1]), "+f"((d)[2]), "+f"((d)[3])      \
                 : "r"((a)[0]), "r"((a)[1]), "r"((a)[2]), "r"((a)[3]),         \
                   "r"(b0), "r"(b1))

// pack (fp16(a), fp16(b)) -> u32 {b<<16 | a}
__device__ __forceinline__ uint32_t pack_f16x2(float a, float b) {
    uint32_t r;
    asm("cvt.rn.f16x2.f32 %0, %1, %2;" : "=r"(r) : "f"(b), "f"(a));
    return r;
}

// ---------------- pre-pass: X -> fp16, swizzled image ----------------
__global__ __launch_bounds__(256)
void build_x_kernel(const float* __restrict__ x) {
    const size_t id = (size_t)blockIdx.x * 256 + threadIdx.x;  // m*KC64 + kc
    const int kc = (int)(id & (KC64 - 1));
    const int m  = (int)(id >> 6);
    const float4* src = reinterpret_cast<const float4*>(x + (size_t)m * K_DIM + kc * 64);

    uint32_t w[32];
#pragma unroll
    for (int t = 0; t < 16; t++) {
        float4 v = src[t];
        w[2 * t + 0] = pack_f16x2(v.x, v.y);
        w[2 * t + 1] = pack_f16x2(v.z, v.w);
    }
    uint8_t* dst = g_xh + id * 128;
    const int r7 = m & 7;
#pragma unroll
    for (int q = 0; q < 8; q++)
        *reinterpret_cast<uint4*>(dst + ((q ^ r7) * 16)) =
            make_uint4(w[4 * q], w[4 * q + 1], w[4 * q + 2], w[4 * q + 3]);
}

// ---------------- pre-pass: NF4 dequant -> fp16, swizzled image ----------
// Each int32 of `packed` holds ONE byte value = 2 nibbles = 2 weights.
// A 64-weight k-chunk spans 32 ints (= 8 int4 loads).
__global__ __launch_bounds__(256)
void build_w_kernel(const int* __restrict__ packed) {
    __shared__ uint16_t lut[16];   // fp16 bits of NF4 level
    if (threadIdx.x < 16)
        lut[threadIdx.x] = (uint16_t)(pack_f16x2(NF4_TAB[threadIdx.x], 0.0f) & 0xFFFFu);
    __syncthreads();

    const size_t id = (size_t)blockIdx.x * 256 + threadIdx.x;  // n*KC64 + kc
    const int kc = (int)(id & (KC64 - 1));
    const int n  = (int)(id >> 6);
    const int4* src = reinterpret_cast<const int4*>(packed) +
                      (size_t)n * (KH / 4) + kc * 8;

    uint32_t w[32];
#pragma unroll
    for (int v4 = 0; v4 < 8; v4++) {
        const int4 pv = src[v4];
        const uint32_t byts[4] = {(uint32_t)pv.x & 255u, (uint32_t)pv.y & 255u,
                                  (uint32_t)pv.z & 255u, (uint32_t)pv.w & 255u};
#pragma unroll
        for (int e = 0; e < 4; e++) {
            const uint32_t b = byts[e];
            // k even = high nibble, k odd = low nibble
            w[4 * v4 + e] = (uint32_t)lut[b >> 4] | ((uint32_t)lut[b & 15u] << 16);
        }
    }
    uint8_t* dst = g_wh + id * 128;
    const int r7 = n & 7;
#pragma unroll
    for (int q = 0; q < 8; q++)
        *reinterpret_cast<uint4*>(dst + ((q ^ r7) * 16)) =
            make_uint4(w[4 * q], w[4 * q + 1], w[4 * q + 2], w[4 * q + 3]);
}

// ---------------- main GEMM: cp.async pipeline + ldmatrix + mma.sync -------
__global__ __launch_bounds__(NTH, 1)
void nf4_hmma_kernel(const float* __restrict__ absmax,
                     const float* __restrict__ bias,
                     float* __restrict__ out) {
    extern __shared__ __align__(1024) uint8_t smem[];
    const uint32_t sbase = (uint32_t)__cvta_generic_to_shared(smem);

    const int tid  = threadIdx.x;
    const int wid  = tid >> 5;
    const int lane = tid & 31;
    const int bm = blockIdx.y * BM;
    const int bn = blockIdx.x * BN;
    const int wm = (wid & 1) * 64;     // 2 warps in m, warptile m=64
    const int wn = (wid >> 1) * 32;    // 8 warps in n, warptile n=32

    // ---- per-lane ldmatrix address components (verified R8/R9) ----
    const int s7 = lane & 7;
    const int rl = s7 + 8 * ((lane >> 3) & 1);       // A row-in-16
    const int pa = lane >> 4;                        // A k-half bit
    const int nl = s7 + 8 * (lane >> 4);             // B n-in-16
    const int kb = (lane >> 3) & 1;                  // B k-half bit
    const uint32_t xlb = (uint32_t)(wm + rl) * 128;
    const uint32_t wlb = (uint32_t)(wn + nl) * 128;

    uint32_t a_sw[4], b_sw[4];   // per k16-step swizzled 16B offsets
#pragma unroll
    for (int ks = 0; ks < 4; ks++) {
        a_sw[ks] = (uint32_t)(((2 * ks + pa) ^ s7) * 16);
        b_sw[ks] = (uint32_t)(((2 * ks + kb) ^ s7) * 16);
    }

    // ---- cp.async producer mapping: identity copy (swizzle baked in) ----
    // X: 1024 16B-chunks -> 2/thread;  W: 2048 -> 4/thread
    auto issue_stage = [&](int c) {
        const uint32_t sb = sbase + (uint32_t)(c & (STAGES - 1)) * STAGE_BYTES;
#pragma unroll
        for (int i = 0; i < 2; i++) {
            const int q = tid + i * NTH;
            const int row = q >> 3, j = q & 7;
            const uint8_t* gx = g_xh + (((size_t)(bm + row)) * KC64 + c) * 128 + j * 16;
            CP_ASYNC16(sb + row * 128 + j * 16, gx);
        }
#pragma unroll
        for (int i = 0; i < 4; i++) {
            const int q = tid + i * NTH;
            const int row = q >> 3, j = q & 7;
            const uint8_t* gw = g_wh + (((size_t)(bn + row)) * KC64 + c) * 128 + j * 16;
            CP_ASYNC16(sb + XS_BYTES + row * 128 + j * 16, gw);
        }
    };

    float acc[4][4][4];
#pragma unroll
    for (int mt = 0; mt < 4; mt++)
#pragma unroll
        for (int nt = 0; nt < 4; nt++)
#pragma unroll
            for (int e = 0; e < 4; e++) acc[mt][nt][e] = 0.0f;

    // ---- prologue: 3 stages in flight ----
    issue_stage(0); CP_COMMIT();
    issue_stage(1); CP_COMMIT();
    issue_stage(2); CP_COMMIT();

    // ---- mainloop ----
    for (int c = 0; c < NCHUNK; c++) {
        CP_WAIT(2);          // group for chunk c complete
        __syncthreads();

        if (c + 3 < NCHUNK) issue_stage(c + 3);
        CP_COMMIT();         // keep group count in lockstep

        const uint32_t sb = sbase + (uint32_t)(c & (STAGES - 1)) * STAGE_BYTES;
        const uint32_t Xb = sb;
        const uint32_t Wb = sb + XS_BYTES;

#pragma unroll
        for (int ks = 0; ks < 4; ks++) {
            uint32_t a[4][4];
#pragma unroll
            for (int mt = 0; mt < 4; mt++)
                LDSM4(a[mt][0], a[mt][1], a[mt][2], a[mt][3],
                      Xb + xlb + (uint32_t)mt * 2048 + a_sw[ks]);
            uint32_t b[2][4];
#pragma unroll
            for (int g = 0; g < 2; g++)
                LDSM4(b[g][0], b[g][1], b[g][2], b[g][3],
                      Wb + wlb + (uint32_t)g * 2048 + b_sw[ks]);
#pragma unroll
            for (int mt = 0; mt < 4; mt++)
#pragma unroll
                for (int nt = 0; nt < 4; nt++) {
                    const int g = nt >> 1, o = (nt & 1) * 2;
                    MMA16816(acc[mt][nt], a[mt], b[g][o], b[g][o + 1]);
                }
        }
    }

    // ---- epilogue: apply absmax + bias, write out ----
#pragma unroll
    for (int nt = 0; nt < 4; nt++) {
        const int col = bn + wn + nt * 8 + 2 * (lane & 3);
        const float2 am = *reinterpret_cast<const float2*>(absmax + col);
        const float2 bi = *reinterpret_cast<const float2*>(bias + col);
#pragma unroll
        for (int mt = 0; mt < 4; mt++) {
            const int m0 = bm + wm + mt * 16 + (lane >> 2);
            float2 o0, o1;
            o0.x = acc[mt][nt][0] * am.x + bi.x;
            o0.y = acc[mt][nt][1] * am.y + bi.y;
            o1.x = acc[mt][nt][2] * am.x + bi.x;
            o1.y = acc[mt][nt][3] * am.y + bi.y;
            *reinterpret_cast<float2*>(out + (size_t)m0 * N_DIM + col) = o0;
            *reinterpret_cast<float2*>(out + (size_t)(m0 + 8) * N_DIM + col) = o1;
        }
    }
}

// ---------------- launch ----------------
extern "C" void kernel_launch(void* const* d_in, const int* in_sizes, int n_in,
                              void* d_out, int out_size) {
    const float* x      = (const float*)d_in[0];
    const int*   packed = (const int*)d_in[1];
    const float* absmax = (const float*)d_in[2];
    const float* bias   = (const float*)d_in[3];
    float*       out    = (float*)d_out;

    build_x_kernel<<<(M_DIM * KC64) / 256, 256>>>(x);
    build_w_kernel<<<(N_DIM * KC64) / 256, 256>>>(packed);

    cudaFuncSetAttribute(nf4_hmma_kernel,
                         cudaFuncAttributeMaxDynamicSharedMemorySize, SMEM_DYN);
    dim3 grid(N_DIM / BN, M_DIM / BM);   // (16, 64)
    nf4_hmma_kernel<<<grid, NTH, SMEM_DYN>>>(absmax, bias, out);
}

// round 13
// speedup vs baseline: 8.7928x; 1.0505x over previous
#include <cuda_runtime.h>
#include <cuda_fp16.h>
#include <cstdint>

// NF4 quantized linear via single-term fp16 mma.sync (sm_103, non-'a' target).
// out[m][n] = sum_k x[m][k] * LUT[nib(packed[n][k])] * absmax[n] + bias[n]
// M=8192, N=4096, K=4096.
//
// fp16(x) * fp16(LUT) with fp32 accumulation: rel err ~2.6e-4 (< 1e-3 tol).
// GEMM (unchanged from R11, at the legacy-HMMA hardware ceiling ~430 TF/s):
// 128x256x64 CTA tile, 512 threads, 4-stage cp.async, ldmatrix, HMMA.
// R12: coalesced pre-passes — 8 lanes cooperate per 128-byte image block so
// LDG/STG are contiguous across lanes (R11 gave each thread a whole block,
// 32 lines per warp instruction -> LSU-wavefront bound, 3.7 TB/s).

#define M_DIM 8192
#define N_DIM 4096
#define K_DIM 4096
#define KC64  (K_DIM / 64)        // 64 K-chunks of 64
#define KH    (K_DIM / 2)         // packed byte count per W row

#define BM 128
#define BN 256
#define NCHUNK KC64               // 64
#define NTH 512
#define STAGES 4
#define XS_BYTES 16384            // 128 rows x 128B
#define WS_BYTES 32768            // 256 rows x 128B
#define STAGE_BYTES (XS_BYTES + WS_BYTES)       // 49152
#define SMEM_DYN (STAGES * STAGE_BYTES)         // 196608

__device__ uint8_t g_xh[(size_t)M_DIM * KC64 * 128];   // 64 MB fp16 X image
__device__ uint8_t g_wh[(size_t)N_DIM * KC64 * 128];   // 32 MB fp16 W image

__constant__ float NF4_TAB[16] = {
    -1.0f, -0.6961928009986877f, -0.5250730514526367f, -0.39491748809814453f,
    -0.28444138169288635f, -0.18477343022823334f, -0.09105003625154495f, 0.0f,
    0.07958029955625534f, 0.16093020141124725f, 0.24611230194568634f,
    0.33791524171829224f, 0.44070982933044434f, 0.5626170039176941f,
    0.7229568362236023f, 1.0f};

// ---------------- PTX helpers (arch-agnostic, sm_80+) ----------------
#define CP_ASYNC16(smem_u32, gptr)                                             \
    asm volatile("cp.async.cg.shared.global [%0], [%1], 16;"                   \
                 :: "r"(smem_u32), "l"(gptr))
#define CP_COMMIT() asm volatile("cp.async.commit_group;" ::: "memory")
#define CP_WAIT(n)  asm volatile("cp.async.wait_group %0;" :: "n"(n) : "memory")

#define LDSM4(r0, r1, r2, r3, addr)                                            \
    asm volatile("ldmatrix.sync.aligned.m8n8.x4.shared.b16 {%0,%1,%2,%3}, [%4];" \
                 : "=r"(r0), "=r"(r1), "=r"(r2), "=r"(r3) : "r"(addr))

#define MMA16816(d, a, b0, b1)                                                 \
    asm volatile("mma.sync.aligned.m16n8k16.row.col.f32.f16.f16.f32 "          \
                 "{%0,%1,%2,%3}, {%4,%5,%6,%7}, {%8,%9}, {%0,%1,%2,%3};"       \
                 : "+f"((d)[0]), "+f"((d)[1]), "+f"((d)[2]), "+f"((d)[3])      \
                 : "r"((a)[0]), "r"((a)[1]), "r"((a)[2]), "r"((a)[3]),         \
                   "r"(b0), "r"(b1))

// pack (fp16(a), fp16(b)) -> u32 {b<<16 | a}
__device__ __forceinline__ uint32_t pack_f16x2(float a, float b) {
    uint32_t r;
    asm("cvt.rn.f16x2.f32 %0, %1, %2;" : "=r"(r) : "f"(b), "f"(a));
    return r;
}

// ---------------- pre-pass: X -> fp16, swizzled image (coalesced) ----------
// 8 lanes per 128B block: lane j reads 32B (8 floats) at j*32, writes one
// swizzled 16B chunk. Consecutive lanes touch consecutive addresses.
__global__ __launch_bounds__(256)
void build_x_kernel(const float* __restrict__ x) {
    const size_t gt = (size_t)blockIdx.x * 256 + threadIdx.x;
    const size_t id = gt >> 3;                 // block index: m*KC64 + kc
    const int    j  = (int)(gt & 7);           // 16B sub-chunk
    const int kc = (int)(id & (KC64 - 1));
    const int m  = (int)(id >> 6);

    const float4* src = reinterpret_cast<const float4*>(
        x + (size_t)m * K_DIM + kc * 64 + j * 8);
    const float4 v0 = src[0];
    const float4 v1 = src[1];
    const uint4 o = make_uint4(pack_f16x2(v0.x, v0.y), pack_f16x2(v0.z, v0.w),
                               pack_f16x2(v1.x, v1.y), pack_f16x2(v1.z, v1.w));
    *reinterpret_cast<uint4*>(g_xh + id * 128 + ((j ^ (m & 7)) * 16)) = o;
}

// ---------------- pre-pass: NF4 dequant -> fp16, swizzled (coalesced) ------
// Each int32 of `packed` holds ONE byte value = 2 nibbles = 2 weights.
// 8 lanes per 128B block: lane j reads one int4 (4 ints = 8 weights),
// writes one swizzled 16B chunk.
__global__ __launch_bounds__(256)
void build_w_kernel(const int* __restrict__ packed) {
    __shared__ uint16_t lut[16];   // fp16 bits of NF4 level
    if (threadIdx.x < 16)
        lut[threadIdx.x] = (uint16_t)(pack_f16x2(NF4_TAB[threadIdx.x], 0.0f) & 0xFFFFu);
    __syncthreads();

    const size_t gt = (size_t)blockIdx.x * 256 + threadIdx.x;
    const size_t id = gt >> 3;                 // block index: n*KC64 + kc
    const int    j  = (int)(gt & 7);
    const int kc = (int)(id & (KC64 - 1));
    const int n  = (int)(id >> 6);

    const int4 pv = reinterpret_cast<const int4*>(packed)
                        [(size_t)n * (KH / 4) + kc * 8 + j];
    const uint32_t byts[4] = {(uint32_t)pv.x & 255u, (uint32_t)pv.y & 255u,
                              (uint32_t)pv.z & 255u, (uint32_t)pv.w & 255u};
    uint32_t w[4];
#pragma unroll
    for (int e = 0; e < 4; e++) {
        const uint32_t b = byts[e];
        // k even = high nibble, k odd = low nibble
        w[e] = (uint32_t)lut[b >> 4] | ((uint32_t)lut[b & 15u] << 16);
    }
    *reinterpret_cast<uint4*>(g_wh + id * 128 + ((j ^ (n & 7)) * 16)) =
        make_uint4(w[0], w[1], w[2], w[3]);
}

// ---------------- main GEMM: cp.async pipeline + ldmatrix + mma.sync -------
// (unchanged from R11 — measured at the legacy-HMMA pipe ceiling)
__global__ __launch_bounds__(NTH, 1)
void nf4_hmma_kernel(const float* __restrict__ absmax,
                     const float* __restrict__ bias,
                     float* __restrict__ out) {
    extern __shared__ __align__(1024) uint8_t smem[];
    const uint32_t sbase = (uint32_t)__cvta_generic_to_shared(smem);

    const int tid  = threadIdx.x;
    const int wid  = tid >> 5;
    const int lane = tid & 31;
    const int bm = blockIdx.y * BM;
    const int bn = blockIdx.x * BN;
    const int wm = (wid & 1) * 64;     // 2 warps in m, warptile m=64
    const int wn = (wid >> 1) * 32;    // 8 warps in n, warptile n=32

    // ---- per-lane ldmatrix address components (verified R8/R9) ----
    const int s7 = lane & 7;
    const int rl = s7 + 8 * ((lane >> 3) & 1);       // A row-in-16
    const int pa = lane >> 4;                        // A k-half bit
    const int nl = s7 + 8 * (lane >> 4);             // B n-in-16
    const int kb = (lane >> 3) & 1;                  // B k-half bit
    const uint32_t xlb = (uint32_t)(wm + rl) * 128;
    const uint32_t wlb = (uint32_t)(wn + nl) * 128;

    uint32_t a_sw[4], b_sw[4];   // per k16-step swizzled 16B offsets
#pragma unroll
    for (int ks = 0; ks < 4; ks++) {
        a_sw[ks] = (uint32_t)(((2 * ks + pa) ^ s7) * 16);
        b_sw[ks] = (uint32_t)(((2 * ks + kb) ^ s7) * 16);
    }

    // ---- cp.async producer mapping: identity copy (swizzle baked in) ----
    // X: 1024 16B-chunks -> 2/thread;  W: 2048 -> 4/thread
    auto issue_stage = [&](int c) {
        const uint32_t sb = sbase + (uint32_t)(c & (STAGES - 1)) * STAGE_BYTES;
#pragma unroll
        for (int i = 0; i < 2; i++) {
            const int q = tid + i * NTH;
            const int row = q >> 3, j = q & 7;
            const uint8_t* gx = g_xh + (((size_t)(bm + row)) * KC64 + c) * 128 + j * 16;
            CP_ASYNC16(sb + row * 128 + j * 16, gx);
        }
#pragma unroll
        for (int i = 0; i < 4; i++) {
            const int q = tid + i * NTH;
            const int row = q >> 3, j = q & 7;
            const uint8_t* gw = g_wh + (((size_t)(bn + row)) * KC64 + c) * 128 + j * 16;
            CP_ASYNC16(sb + XS_BYTES + row * 128 + j * 16, gw);
        }
    };

    float acc[4][4][4];
#pragma unroll
    for (int mt = 0; mt < 4; mt++)
#pragma unroll
        for (int nt = 0; nt < 4; nt++)
#pragma unroll
            for (int e = 0; e < 4; e++) acc[mt][nt][e] = 0.0f;

    // ---- prologue: 3 stages in flight ----
    issue_stage(0); CP_COMMIT();
    issue_stage(1); CP_COMMIT();
    issue_stage(2); CP_COMMIT();

    // ---- mainloop ----
    for (int c = 0; c < NCHUNK; c++) {
        CP_WAIT(2);          // group for chunk c complete
        __syncthreads();

        if (c + 3 < NCHUNK) issue_stage(c + 3);
        CP_COMMIT();         // keep group count in lockstep

        const uint32_t sb = sbase + (uint32_t)(c & (STAGES - 1)) * STAGE_BYTES;
        const uint32_t Xb = sb;
        const uint32_t Wb = sb + XS_BYTES;

#pragma unroll
        for (int ks = 0; ks < 4; ks++) {
            uint32_t a[4][4];
#pragma unroll
            for (int mt = 0; mt < 4; mt++)
                LDSM4(a[mt][0], a[mt][1], a[mt][2], a[mt][3],
                      Xb + xlb + (uint32_t)mt * 2048 + a_sw[ks]);
            uint32_t b[2][4];
#pragma unroll
            for (int g = 0; g < 2; g++)
                LDSM4(b[g][0], b[g][1], b[g][2], b[g][3],
                      Wb + wlb + (uint32_t)g * 2048 + b_sw[ks]);
#pragma unroll
            for (int mt = 0; mt < 4; mt++)
#pragma unroll
                for (int nt = 0; nt < 4; nt++) {
                    const int g = nt >> 1, o = (nt & 1) * 2;
                    MMA16816(acc[mt][nt], a[mt], b[g][o], b[g][o + 1]);
                }
        }
    }

    // ---- epilogue: apply absmax + bias, write out ----
#pragma unroll
    for (int nt = 0; nt < 4; nt++) {
        const int col = bn + wn + nt * 8 + 2 * (lane & 3);
        const float2 am = *reinterpret_cast<const float2*>(absmax + col);
        const float2 bi = *reinterpret_cast<const float2*>(bias + col);
#pragma unroll
        for (int mt = 0; mt < 4; mt++) {
            const int m0 = bm + wm + mt * 16 + (lane >> 2);
            float2 o0, o1;
            o0.x = acc[mt][nt][0] * am.x + bi.x;
            o0.y = acc[mt][nt][1] * am.y + bi.y;
            o1.x = acc[mt][nt][2] * am.x + bi.x;
            o1.y = acc[mt][nt][3] * am.y + bi.y;
            *reinterpret_cast<float2*>(out + (size_t)m0 * N_DIM + col) = o0;
            *reinterpret_cast<float2*>(out + (size_t)(m0 + 8) * N_DIM + col) = o1;
        }
    }
}

// ---------------- launch ----------------
extern "C" void kernel_launch(void* const* d_in, const int* in_sizes, int n_in,
                              void* d_out, int out_size) {
    const float* x      = (const float*)d_in[0];
    const int*   packed = (const int*)d_in[1];
    const float* absmax = (const float*)d_in[2];
    const float* bias   = (const float*)d_in[3];
    float*       out    = (float*)d_out;

    build_x_kernel<<<((size_t)M_DIM * KC64 * 8) / 256, 256>>>(x);
    build_w_kernel<<<((size_t)N_DIM * KC64 * 8) / 256, 256>>>(packed);

    cudaFuncSetAttribute(nf4_hmma_kernel,
                         cudaFuncAttributeMaxDynamicSharedMemorySize, SMEM_DYN);
    dim3 grid(N_DIM / BN, M_DIM / BM);   // (16, 64)
    nf4_hmma_kernel<<<grid, NTH, SMEM_DYN>>>(absmax, bias, out);
}

// round 14
// speedup vs baseline: 8.9542x; 1.0184x over previous
#include <cuda_runtime.h>
#include <cuda_fp16.h>
#include <cstdint>

// NF4 quantized linear via single-term fp16 mma.sync (sm_103, non-'a' target).
// out[m][n] = sum_k x[m][k] * LUT[nib(packed[n][k])] * absmax[n] + bias[n]
// M=8192, N=4096, K=4096.
//
// fp16(x) * fp16(LUT) with fp32 accumulation: rel err ~2.6e-4 (< 1e-3 tol).
// R13: BK=128 with 2 x 96KB smem stages (32 K-chunks instead of 64) to
// amortize per-chunk barrier/drain overhead over 2x the MMAs. Images and
// pre-passes unchanged from R12 (GEMM loads two adjacent 128B k64-blocks
// per row into one 256B smem row; each half keeps its own XOR swizzle).

#define M_DIM 8192
#define N_DIM 4096
#define K_DIM 4096
#define KC64  (K_DIM / 64)        // 64 k64-blocks per row (image layout)
#define KH    (K_DIM / 2)         // packed byte count per W row

#define BM 128
#define BN 256
#define NCHUNK 32                 // K-chunks of 128
#define NTH 512
#define STAGES 2
#define XS_BYTES 32768            // 128 rows x 256B
#define WS_BYTES 65536            // 256 rows x 256B
#define STAGE_BYTES (XS_BYTES + WS_BYTES)       // 98304
#define SMEM_DYN (STAGES * STAGE_BYTES)         // 196608

__device__ uint8_t g_xh[(size_t)M_DIM * KC64 * 128];   // 64 MB fp16 X image
__device__ uint8_t g_wh[(size_t)N_DIM * KC64 * 128];   // 32 MB fp16 W image

__constant__ float NF4_TAB[16] = {
    -1.0f, -0.6961928009986877f, -0.5250730514526367f, -0.39491748809814453f,
    -0.28444138169288635f, -0.18477343022823334f, -0.09105003625154495f, 0.0f,
    0.07958029955625534f, 0.16093020141124725f, 0.24611230194568634f,
    0.33791524171829224f, 0.44070982933044434f, 0.5626170039176941f,
    0.7229568362236023f, 1.0f};

// ---------------- PTX helpers (arch-agnostic, sm_80+) ----------------
#define CP_ASYNC16(smem_u32, gptr)                                             \
    asm volatile("cp.async.cg.shared.global [%0], [%1], 16;"                   \
                 :: "r"(smem_u32), "l"(gptr))
#define CP_COMMIT() asm volatile("cp.async.commit_group;" ::: "memory")
#define CP_WAIT(n)  asm volatile("cp.async.wait_group %0;" :: "n"(n) : "memory")

#define LDSM4(r0, r1, r2, r3, addr)                                            \
    asm volatile("ldmatrix.sync.aligned.m8n8.x4.shared.b16 {%0,%1,%2,%3}, [%4];" \
                 : "=r"(r0), "=r"(r1), "=r"(r2), "=r"(r3) : "r"(addr))

#define MMA16816(d, a, b0, b1)                                                 \
    asm volatile("mma.sync.aligned.m16n8k16.row.col.f32.f16.f16.f32 "          \
                 "{%0,%1,%2,%3}, {%4,%5,%6,%7}, {%8,%9}, {%0,%1,%2,%3};"       \
                 : "+f"((d)[0]), "+f"((d)[1]), "+f"((d)[2]), "+f"((d)[3])      \
                 : "r"((a)[0]), "r"((a)[1]), "r"((a)[2]), "r"((a)[3]),         \
                   "r"(b0), "r"(b1))

// pack (fp16(a), fp16(b)) -> u32 {b<<16 | a}
__device__ __forceinline__ uint32_t pack_f16x2(float a, float b) {
    uint32_t r;
    asm("cvt.rn.f16x2.f32 %0, %1, %2;" : "=r"(r) : "f"(b), "f"(a));
    return r;
}

// ---------------- pre-pass: X -> fp16, swizzled image (coalesced) ----------
__global__ __launch_bounds__(256)
void build_x_kernel(const float* __restrict__ x) {
    const size_t gt = (size_t)blockIdx.x * 256 + threadIdx.x;
    const size_t id = gt >> 3;                 // block index: m*KC64 + kc
    const int    j  = (int)(gt & 7);           // 16B sub-chunk
    const int kc = (int)(id & (KC64 - 1));
    const int m  = (int)(id >> 6);

    const float4* src = reinterpret_cast<const float4*>(
        x + (size_t)m * K_DIM + kc * 64 + j * 8);
    const float4 v0 = src[0];
    const float4 v1 = src[1];
    const uint4 o = make_uint4(pack_f16x2(v0.x, v0.y), pack_f16x2(v0.z, v0.w),
                               pack_f16x2(v1.x, v1.y), pack_f16x2(v1.z, v1.w));
    *reinterpret_cast<uint4*>(g_xh + id * 128 + ((j ^ (m & 7)) * 16)) = o;
}

// ---------------- pre-pass: NF4 dequant -> fp16, swizzled (coalesced) ------
__global__ __launch_bounds__(256)
void build_w_kernel(const int* __restrict__ packed) {
    __shared__ uint16_t lut[16];   // fp16 bits of NF4 level
    if (threadIdx.x < 16)
        lut[threadIdx.x] = (uint16_t)(pack_f16x2(NF4_TAB[threadIdx.x], 0.0f) & 0xFFFFu);
    __syncthreads();

    const size_t gt = (size_t)blockIdx.x * 256 + threadIdx.x;
    const size_t id = gt >> 3;                 // block index: n*KC64 + kc
    const int    j  = (int)(gt & 7);
    const int kc = (int)(id & (KC64 - 1));
    const int n  = (int)(id >> 6);

    const int4 pv = reinterpret_cast<const int4*>(packed)
                        [(size_t)n * (KH / 4) + kc * 8 + j];
    const uint32_t byts[4] = {(uint32_t)pv.x & 255u, (uint32_t)pv.y & 255u,
                              (uint32_t)pv.z & 255u, (uint32_t)pv.w & 255u};
    uint32_t w[4];
#pragma unroll
    for (int e = 0; e < 4; e++) {
        const uint32_t b = byts[e];
        // k even = high nibble, k odd = low nibble
        w[e] = (uint32_t)lut[b >> 4] | ((uint32_t)lut[b & 15u] << 16);
    }
    *reinterpret_cast<uint4*>(g_wh + id * 128 + ((j ^ (n & 7)) * 16)) =
        make_uint4(w[0], w[1], w[2], w[3]);
}

// ---------------- main GEMM: BK=128, 2-stage cp.async, ldmatrix, HMMA ------
__global__ __launch_bounds__(NTH, 1)
void nf4_hmma_kernel(const float* __restrict__ absmax,
                     const float* __restrict__ bias,
                     float* __restrict__ out) {
    extern __shared__ __align__(1024) uint8_t smem[];
    const uint32_t sbase = (uint32_t)__cvta_generic_to_shared(smem);

    const int tid  = threadIdx.x;
    const int wid  = tid >> 5;
    const int lane = tid & 31;
    const int bm = blockIdx.y * BM;
    const int bn = blockIdx.x * BN;
    const int wm = (wid & 1) * 64;     // 2 warps in m, warptile m=64
    const int wn = (wid >> 1) * 32;    // 8 warps in n, warptile n=32

    // ---- per-lane ldmatrix address components (verified R8-R12) ----
    const int s7 = lane & 7;
    const int rl = s7 + 8 * ((lane >> 3) & 1);       // A row-in-16
    const int pa = lane >> 4;                        // A k-half bit
    const int nl = s7 + 8 * (lane >> 4);             // B n-in-16
    const int kb = (lane >> 3) & 1;                  // B k-half bit
    // smem rows are 256B: [half0 128B | half1 128B], each half XOR-swizzled
    const uint32_t xlb = (uint32_t)(wm + rl) * 256;
    const uint32_t wlb = (uint32_t)(wn + nl) * 256;

    uint32_t a_sw[8], b_sw[8];   // per k16-step offsets within the 256B row
#pragma unroll
    for (int ks = 0; ks < 8; ks++) {
        const int half = ks >> 2, k4 = ks & 3;
        a_sw[ks] = (uint32_t)(half * 128 + ((2 * k4 + pa) ^ s7) * 16);
        b_sw[ks] = (uint32_t)(half * 128 + ((2 * k4 + kb) ^ s7) * 16);
    }

    // ---- cp.async producer: identity copy of two k64 image blocks per row --
    // X: 128 rows x 16 sub-chunks = 2048 -> 4/thread
    // W: 256 rows x 16 sub-chunks = 4096 -> 8/thread
    auto issue_stage = [&](int c) {
        const uint32_t sb = sbase + (uint32_t)(c & (STAGES - 1)) * STAGE_BYTES;
#pragma unroll
        for (int i = 0; i < 4; i++) {
            const int q = tid + i * NTH;
            const int row = q >> 4, sub = q & 15;
            const int half = sub >> 3, j = sub & 7;
            const uint8_t* gx =
                g_xh + (((size_t)(bm + row)) * KC64 + 2 * c + half) * 128 + j * 16;
            CP_ASYNC16(sb + row * 256 + half * 128 + j * 16, gx);
        }
#pragma unroll
        for (int i = 0; i < 8; i++) {
            const int q = tid + i * NTH;
            const int row = q >> 4, sub = q & 15;
            const int half = sub >> 3, j = sub & 7;
            const uint8_t* gw =
                g_wh + (((size_t)(bn + row)) * KC64 + 2 * c + half) * 128 + j * 16;
            CP_ASYNC16(sb + XS_BYTES + row * 256 + half * 128 + j * 16, gw);
        }
    };

    float acc[4][4][4];
#pragma unroll
    for (int mt = 0; mt < 4; mt++)
#pragma unroll
        for (int nt = 0; nt < 4; nt++)
#pragma unroll
            for (int e = 0; e < 4; e++) acc[mt][nt][e] = 0.0f;

    // ---- prologue: both stages in flight ----
    issue_stage(0); CP_COMMIT();
    issue_stage(1); CP_COMMIT();

    // ---- mainloop ----
    for (int c = 0; c < NCHUNK; c++) {
        CP_WAIT(1);          // group for chunk c complete (1 group may pend)
        __syncthreads();     // all threads' waits done -> stage visible to all

        const uint32_t sb = sbase + (uint32_t)(c & (STAGES - 1)) * STAGE_BYTES;
        const uint32_t Xb = sb;
        const uint32_t Wb = sb + XS_BYTES;

#pragma unroll
        for (int ks = 0; ks < 8; ks++) {
            uint32_t a[4][4];
#pragma unroll
            for (int mt = 0; mt < 4; mt++)
                LDSM4(a[mt][0], a[mt][1], a[mt][2], a[mt][3],
                      Xb + xlb + (uint32_t)mt * 4096 + a_sw[ks]);
            uint32_t b[2][4];
#pragma unroll
            for (int g = 0; g < 2; g++)
                LDSM4(b[g][0], b[g][1], b[g][2], b[g][3],
                      Wb + wlb + (uint32_t)g * 4096 + b_sw[ks]);
#pragma unroll
            for (int mt = 0; mt < 4; mt++)
#pragma unroll
                for (int nt = 0; nt < 4; nt++) {
                    const int g = nt >> 1, o = (nt & 1) * 2;
                    MMA16816(acc[mt][nt], a[mt], b[g][o], b[g][o + 1]);
                }
        }

        __syncthreads();     // all warps done reading stage c&1 before refill
        if (c + 2 < NCHUNK) issue_stage(c + 2);
        CP_COMMIT();         // keep group count in lockstep
    }

    // ---- epilogue: apply absmax + bias, write out ----
#pragma unroll
    for (int nt = 0; nt < 4; nt++) {
        const int col = bn + wn + nt * 8 + 2 * (lane & 3);
        const float2 am = *reinterpret_cast<const float2*>(absmax + col);
        const float2 bi = *reinterpret_cast<const float2*>(bias + col);
#pragma unroll
        for (int mt = 0; mt < 4; mt++) {
            const int m0 = bm + wm + mt * 16 + (lane >> 2);
            float2 o0, o1;
            o0.x = acc[mt][nt][0] * am.x + bi.x;
            o0.y = acc[mt][nt][1] * am.y + bi.y;
            o1.x = acc[mt][nt][2] * am.x + bi.x;
            o1.y = acc[mt][nt][3] * am.y + bi.y;
            *reinterpret_cast<float2*>(out + (size_t)m0 * N_DIM + col) = o0;
            *reinterpret_cast<float2*>(out + (size_t)(m0 + 8) * N_DIM + col) = o1;
        }
    }
}

// ---------------- launch ----------------
extern "C" void kernel_launch(void* const* d_in, const int* in_sizes, int n_in,
                              void* d_out, int out_size) {
    const float* x      = (const float*)d_in[0];
    const int*   packed = (const int*)d_in[1];
    const float* absmax = (const float*)d_in[2];
    const float* bias   = (const float*)d_in[3];
    float*       out    = (float*)d_out;

    build_x_kernel<<<((size_t)M_DIM * KC64 * 8) / 256, 256>>>(x);
    build_w_kernel<<<((size_t)N_DIM * KC64 * 8) / 256, 256>>>(packed);

    cudaFuncSetAttribute(nf4_hmma_kernel,
                         cudaFuncAttributeMaxDynamicSharedMemorySize, SMEM_DYN);
    dim3 grid(N_DIM / BN, M_DIM / BM);   // (16, 64)
    nf4_hmma_kernel<<<grid, NTH, SMEM_DYN>>>(absmax, bias, out);
}